// round 2
// baseline (speedup 1.0000x reference)
#include <cuda_runtime.h>

#define THREADS 256
#define BT 8            // batch elements per CTA
#define TP 72           // t1g row pitch in floats (pad: 72 mod 32 = 8 -> conflict-free STS)

// Merged TT cores, precomputed on-device each launch (cheap: ~4 MFLOP total).
// gW01r layout: chunk (o0*8+c) of 16 rows [o1*2+r2p][m=i0*8+i1]   (64 chunks x 16 x 64)
// gW23T layout: [k = r2*64+i2*8+i3][o23 = o2*8+o3]                 (1024 x 64)
__device__ __align__(16) float gW01r[65536];
__device__ __align__(16) float gW23T[65536];

__global__ void tt_pre(const float* __restrict__ w0, const float* __restrict__ w1,
                       const float* __restrict__ w2, const float* __restrict__ w3) {
    int tid = blockIdx.x * blockDim.x + threadIdx.x;
    if (tid < 65536) {
        // W01[(o0,o1,r2)][(i0,i1)] = sum_r1 w0[o0*16+r1][i0] * w1[o1*16+r2][r1*8+i1]
        int m  = tid & 63;
        int r2 = (tid >> 6) & 15;
        int oo = tid >> 10;            // o0*8+o1, in [0,64)
        int o0 = oo >> 3, o1 = oo & 7;
        int i0 = m >> 3,  i1 = m & 7;
        float s = 0.f;
        #pragma unroll
        for (int r1 = 0; r1 < 16; r1++)
            s += w0[(o0*16 + r1)*8 + i0] * w1[(o1*16 + r2)*128 + r1*8 + i1];
        int c = r2 >> 1, r2p = r2 & 1;
        gW01r[((o0*8 + c)*16 + o1*2 + r2p)*64 + m] = s;
    } else if (tid < 131072) {
        // W23[(o2,o3)][(r2,i2,i3)] = sum_r3 w2[o2*16+r3][r2*8+i2] * w3[o3][r3*8+i3]
        int t = tid - 65536;
        int o23 = t & 63;
        int k = t >> 6;                 // r2*64 + i2*8 + i3, in [0,1024)
        int r2 = k >> 6, i2 = (k >> 3) & 7, i3 = k & 7;
        int o2 = o23 >> 3, o3 = o23 & 7;
        float s = 0.f;
        #pragma unroll
        for (int r3 = 0; r3 < 16; r3++)
            s += w2[(o2*16 + r3)*128 + r2*8 + i2] * w3[o3*128 + r3*8 + i3];
        gW23T[k*64 + o23] = s;
    }
}

// Fused main kernel: per CTA, BT=8 batch elements.
//   Phase A (per o0-group g, r2-chunk c):  t1[16 x 512] = W01chunk[16x64] @ Xs[64x512]
//   Phase B:                               acc[64 x 64] += W23chunk^T-slice @ t1
// Output out[b][ (g*8+j)*64 + o23 ] accumulated over the 8 c-chunks.
__global__ __launch_bounds__(THREADS, 1)
void tt_main(const float* __restrict__ x, const float* __restrict__ bias,
             float* __restrict__ out) {
    extern __shared__ float smf[];
    float* Xs    = smf;                   // 64 rows x 512 cols (col = q*8 + b)   128 KB
    float* t1g   = smf + 32768;           // 128 rows x TP  (row k2=r2p*64+q, col jb=j*8+b)
    float* W23c  = t1g + 128 * TP;        // 128 x 64   ([k][o23])                32 KB
    float* W01cT = W23c + 8192;           // 64 x 16    ([m][row])                 4 KB

    const int tid = threadIdx.x;
    const long long b0 = (long long)blockIdx.x * BT;

    // ---- load X tile: Xs[m][q*8+bl] = x[b0+bl][m*64+q] ----
    {
        const float4* xp4 = (const float4*)(x + b0 * 4096);
        #pragma unroll 4
        for (int e = tid; e < BT * 1024; e += THREADS) {
            float4 v = xp4[e];
            int idx = e * 4;
            int bl = idx >> 12, m = (idx >> 6) & 63, q = idx & 63;
            float* d = &Xs[m*512 + q*8 + bl];
            d[0] = v.x; d[8] = v.y; d[16] = v.z; d[24] = v.w;
        }
    }

    const int rgA  = tid >> 7;      // Phase A: row group (0..1) -> rows rgA*8+v
    const int cgA  = tid & 127;     // Phase A: col group -> cols cgA*4+u
    const int o23g = tid & 15;      // Phase B: o23 = o23g*4+u
    const int jbg  = tid >> 4;      // Phase B: jb  = jbg*4+w

    float acc[4][4];

    for (int g = 0; g < 8; g++) {
        #pragma unroll
        for (int u = 0; u < 4; u++)
            #pragma unroll
            for (int w = 0; w < 4; w++) acc[u][w] = 0.f;

        for (int c = 0; c < 8; c++) {
            __syncthreads();  // previous readers of W23c/t1g done (also orders X load)

            // stage W01 chunk transposed: W01cT[m][row], row = o1*2+r2p
            {
                const float* src = gW01r + (g*8 + c) * 16 * 64;
                #pragma unroll
                for (int e = tid; e < 1024; e += THREADS) {
                    int row = e >> 6, m = e & 63;
                    W01cT[m*16 + row] = src[e];
                }
            }
            // stage W23 chunk (contiguous 32 KB)
            {
                const float4* src = (const float4*)(gW23T + c * 128 * 64);
                float4* dst = (float4*)W23c;
                #pragma unroll
                for (int e = tid; e < 2048; e += THREADS) dst[e] = src[e];
            }
            __syncthreads();

            // ---- Phase A: 16x512 = 16x64 @ 64x512, thread tile 8 rows x 4 cols ----
            {
                float ta[8][4];
                #pragma unroll
                for (int v = 0; v < 8; v++)
                    #pragma unroll
                    for (int u = 0; u < 4; u++) ta[v][u] = 0.f;

                const float* xcol = Xs + cgA * 4;
                const float* arow = W01cT + rgA * 8;
                #pragma unroll 4
                for (int m = 0; m < 64; m++) {
                    float4 xv = *(const float4*)(xcol + m * 512);
                    float4 a0 = *(const float4*)(arow + m * 16);
                    float4 a1 = *(const float4*)(arow + m * 16 + 4);
                    float av[8] = {a0.x, a0.y, a0.z, a0.w, a1.x, a1.y, a1.z, a1.w};
                    float xr[4] = {xv.x, xv.y, xv.z, xv.w};
                    #pragma unroll
                    for (int v = 0; v < 8; v++)
                        #pragma unroll
                        for (int u = 0; u < 4; u++)
                            ta[v][u] += av[v] * xr[u];
                }
                // store t1g: row rgA*8+v -> (j=row>>1, r2p=row&1); col cgA*4 -> (q=cgA>>1, b base)
                int q  = cgA >> 1;
                int bb = (cgA & 1) * 4;
                #pragma unroll
                for (int v = 0; v < 8; v++) {
                    int row = rgA*8 + v;
                    int j = row >> 1, r2p = row & 1;
                    *(float4*)(t1g + (r2p*64 + q)*TP + j*8 + bb) =
                        make_float4(ta[v][0], ta[v][1], ta[v][2], ta[v][3]);
                }
            }
            __syncthreads();

            // ---- Phase B: acc[o23][jb] += sum_k W23c[k][o23] * t1g[k][jb] ----
            {
                const float* wp = W23c + o23g * 4;
                const float* tp = t1g  + jbg  * 4;
                #pragma unroll 8
                for (int k = 0; k < 128; k++) {
                    float4 wv = *(const float4*)(wp + k * 64);
                    float4 tv = *(const float4*)(tp + k * TP);
                    float wr[4] = {wv.x, wv.y, wv.z, wv.w};
                    float tr[4] = {tv.x, tv.y, tv.z, tv.w};
                    #pragma unroll
                    for (int u = 0; u < 4; u++)
                        #pragma unroll
                        for (int w = 0; w < 4; w++)
                            acc[u][w] += wr[u] * tr[w];
                }
            }
        }

        // ---- epilogue for group g: out[b][(g*8+j)*64 + o23] = acc + bias ----
        {
            int j = jbg >> 1;
            int bbase = (jbg & 1) * 4;
            int obase = (g*8 + j)*64 + o23g*4;
            float4 bv = *(const float4*)(bias + obase);
            #pragma unroll
            for (int w = 0; w < 4; w++) {
                int b = bbase + w;
                float4 r = make_float4(acc[0][w] + bv.x, acc[1][w] + bv.y,
                                       acc[2][w] + bv.z, acc[3][w] + bv.w);
                *(float4*)(out + (b0 + b) * 4096 + obase) = r;
            }
        }
    }
}

extern "C" void kernel_launch(void* const* d_in, const int* in_sizes, int n_in,
                              void* d_out, int out_size) {
    const float* x    = (const float*)d_in[0];
    const float* w0   = (const float*)d_in[1];
    const float* w1   = (const float*)d_in[2];
    const float* w2   = (const float*)d_in[3];
    const float* w3   = (const float*)d_in[4];
    const float* bias = (const float*)d_in[5];
    float* out = (float*)d_out;

    // Precompute merged cores (deterministic, every call). 131072 threads.
    tt_pre<<<512, THREADS>>>(w0, w1, w2, w3);

    const int smem_bytes = (32768 + 128*TP + 8192 + 1024) * (int)sizeof(float); // 204800 B
    cudaFuncSetAttribute(tt_main, cudaFuncAttributeMaxDynamicSharedMemorySize, smem_bytes);
    tt_main<<<16384 / BT, THREADS, smem_bytes>>>(x, bias, out);
}

// round 4
// speedup vs baseline: 3.8147x; 3.8147x over previous
#include <cuda_runtime.h>
#include <cstdint>

#define THREADS 256

// ---------------- helpers ----------------
__device__ __forceinline__ uint32_t smem_u32(const void* p){
    uint32_t a;
    asm("{ .reg .u64 t; cvta.to.shared.u64 t, %1; cvt.u32.u64 %0, t; }" : "=r"(a) : "l"(p));
    return a;
}
__device__ __forceinline__ uint32_t f2tf32(float f){
    uint32_t u; asm("cvt.rna.tf32.f32 %0, %1;" : "=r"(u) : "f"(f)); return u;
}
__device__ __forceinline__ void mma1688(float d[4], const uint32_t a[4], const uint32_t b[2]){
    asm volatile("mma.sync.aligned.m16n8k8.row.col.f32.tf32.tf32.f32 "
        "{%0,%1,%2,%3}, {%4,%5,%6,%7}, {%8,%9}, {%0,%1,%2,%3};"
        : "+f"(d[0]), "+f"(d[1]), "+f"(d[2]), "+f"(d[3])
        : "r"(a[0]), "r"(a[1]), "r"(a[2]), "r"(a[3]), "r"(b[0]), "r"(b[1]));
}
#define CPA16(d, s)  asm volatile("cp.async.cg.shared.global [%0], [%1], 16;" :: "r"(d), "l"(s))
#define CPA_COMMIT() asm volatile("cp.async.commit_group;" ::: "memory")
#define CPA_WAIT0()  asm volatile("cp.async.wait_group 0;" ::: "memory")

// ---------------- merged weights, fragment-ordered, tf32-rounded ----------------
// Both arrays: 16 chunks (r2) x 4096 floats.
// Chunk layout = mma.sync B-fragment order: fi = ((kk*8 + nt)*32 + lane)*2 + reg
//   element: k = kk*8 + (lane&3) + 4*reg,  n = nt*8 + (lane>>2)
// gW01f: k = m (i0,i1), n = oo (o0,o1).   gW23f: k = q (i2,i3), n = o23 (o2,o3).
__device__ __align__(16) float gW01f[65536];
__device__ __align__(16) float gW23f[65536];

__global__ void tt_pre(const float* __restrict__ w0, const float* __restrict__ w1,
                       const float* __restrict__ w2, const float* __restrict__ w3) {
    int tid = blockIdx.x * blockDim.x + threadIdx.x;
    if (tid < 65536) {
        int c    = tid >> 12;          // r2 chunk
        int fi   = tid & 4095;
        int reg  = fi & 1;
        int lane = (fi >> 1) & 31;
        int nt   = (fi >> 6) & 7;
        int kk   = fi >> 9;
        int m  = kk*8 + (lane & 3) + 4*reg;   // (i0,i1)
        int oo = nt*8 + (lane >> 2);          // (o0,o1)
        int o0 = oo >> 3, o1 = oo & 7;
        int i0 = m >> 3,  i1 = m & 7;
        float s = 0.f;
        #pragma unroll
        for (int r1 = 0; r1 < 16; r1++)
            s += w0[(o0*16 + r1)*8 + i0] * w1[(o1*16 + c)*128 + r1*8 + i1];
        gW01f[c*4096 + fi] = __uint_as_float(f2tf32(s));
    } else if (tid < 131072) {
        int t    = tid - 65536;
        int c    = t >> 12;
        int fi   = t & 4095;
        int reg  = fi & 1;
        int lane = (fi >> 1) & 31;
        int nt   = (fi >> 6) & 7;
        int kk   = fi >> 9;
        int q   = kk*8 + (lane & 3) + 4*reg;  // (i2,i3)
        int o23 = nt*8 + (lane >> 2);         // (o2,o3)
        int o2 = o23 >> 3, o3 = o23 & 7;
        int i2 = q >> 3,   i3 = q & 7;
        float s = 0.f;
        #pragma unroll
        for (int r3 = 0; r3 < 16; r3++)
            s += w2[(o2*16 + r3)*128 + c*8 + i2] * w3[o3*128 + r3*8 + i3];
        gW23f[c*4096 + fi] = __uint_as_float(f2tf32(s));
    }
}

// ---------------- SMEM map (floats) ----------------
// A1F [0,16384)      : X fragments, rows (b*64+q), k=m.  16 Mtiles x 8 ksteps x 32 lanes x 4
// A2F [16384,32768)  : t1^T fragments, rows (b*64+oo), k=q. same shape
// B1F [32768,+2*4096): W01 chunk double-buffer
// B2F [40960,+2*4096): W23 chunk double-buffer
#define SMF_TOTAL 49152

__global__ __launch_bounds__(THREADS, 1)
void tt_mma(const float* __restrict__ x, const float* __restrict__ bias,
            float* __restrict__ out) {
    extern __shared__ float smf[];
    float* A1F = smf;
    float* A2F = smf + 16384;
    float* B1F = smf + 32768;
    float* B2F = smf + 40960;

    const int tid  = threadIdx.x;
    const int wid  = tid >> 5;
    const int lane = tid & 31;
    const uint32_t sb = smem_u32(smf);
    const uint32_t B1a = sb + 32768u*4u;
    const uint32_t B2a = sb + 40960u*4u;

    // prefetch weight chunk 0 (16KB each, 1024 float4 per array)
    {
        const float4* s01 = (const float4*)gW01f;
        const float4* s23 = (const float4*)gW23f;
        #pragma unroll
        for (int i = 0; i < 4; i++) CPA16(B1a + (tid + i*256)*16, s01 + tid + i*256);
        #pragma unroll
        for (int i = 0; i < 4; i++) CPA16(B2a + (tid + i*256)*16, s23 + tid + i*256);
        CPA_COMMIT();
    }

    // ---- stage X (4 batch rows) into A1 fragment layout (tf32-rounded) ----
    const long long b0 = (long long)blockIdx.x * 4;
    {
        const float4* xp = (const float4*)(x + b0 * 4096);
        #pragma unroll 4
        for (int e = tid; e < 4096; e += THREADS) {
            float4 v = xp[e];
            int idx = e * 4;
            int b = idx >> 12, m = (idx >> 6) & 63, q = idx & 63;  // q % 4 == 0
            int kk = m >> 3;
            int rhi = ((m & 7) >> 2);                 // k-half bit
            int ld  = (m & 3);
            float vv[4] = {v.x, v.y, v.z, v.w};
            #pragma unroll
            for (int j = 0; j < 4; j++) {
                int row = b*64 + q + j;
                int tile = row >> 4, r = row & 15;
                int ln = (r & 7)*4 + ld;
                int rg = (r >> 3) + 2*rhi;
                A1F[((tile*8 + kk)*32 + ln)*4 + rg] = __uint_as_float(f2tf32(vv[j]));
            }
        }
    }

    float acc[2][8][4];
    #pragma unroll
    for (int mt = 0; mt < 2; mt++)
        #pragma unroll
        for (int nt = 0; nt < 8; nt++)
            #pragma unroll
            for (int r = 0; r < 4; r++) acc[mt][nt][r] = 0.f;

    const int g = lane >> 2, tq = lane & 3;

    for (int c = 0; c < 16; c++) {
        const int cb = c & 1;
        CPA_WAIT0();
        __syncthreads();   // weights visible; A2F WAR vs prev stage-2 reads cleared

        if (c < 15) {      // prefetch next chunk into other buffer
            const int nb = cb ^ 1;
            const float4* s01 = (const float4*)(gW01f + (c + 1)*4096);
            const float4* s23 = (const float4*)(gW23f + (c + 1)*4096);
            #pragma unroll
            for (int i = 0; i < 4; i++) CPA16(B1a + nb*16384 + (tid + i*256)*16, s01 + tid + i*256);
            #pragma unroll
            for (int i = 0; i < 4; i++) CPA16(B2a + nb*16384 + (tid + i*256)*16, s23 + tid + i*256);
            CPA_COMMIT();
        }

        // ---- stage 1: D1[(b,q)][oo] = A1 @ W01_c ; scatter-transpose into A2F ----
        const float* B1 = B1F + cb*4096;
        #pragma unroll
        for (int mt = 0; mt < 2; mt++) {
            const int tile = wid*2 + mt;
            float d[8][4];
            #pragma unroll
            for (int nt = 0; nt < 8; nt++)
                #pragma unroll
                for (int r = 0; r < 4; r++) d[nt][r] = 0.f;

            #pragma unroll
            for (int kk = 0; kk < 8; kk++) {
                float4 af = *(const float4*)(A1F + ((tile*8 + kk)*32 + lane)*4);
                uint32_t a[4] = {__float_as_uint(af.x), __float_as_uint(af.y),
                                 __float_as_uint(af.z), __float_as_uint(af.w)};
                #pragma unroll
                for (int nt = 0; nt < 8; nt++) {
                    float2 bf = *(const float2*)(B1 + ((kk*8 + nt)*32 + lane)*2);
                    uint32_t b[2] = {__float_as_uint(bf.x), __float_as_uint(bf.y)};
                    mma1688(d[nt], a, b);
                }
            }
            // scatter: element (row=(b,q), col=oo) -> A2 row'=(b,oo), k'=q
            #pragma unroll
            for (int nt = 0; nt < 8; nt++)
                #pragma unroll
                for (int r = 0; r < 4; r++) {
                    int orow = tile*16 + g + 8*(r >> 1);
                    int oo   = nt*8 + 2*tq + (r & 1);
                    int b    = orow >> 6, q = orow & 63;
                    int row2 = b*64 + oo;
                    int t2 = row2 >> 4, rr = row2 & 15;
                    int ln = (rr & 7)*4 + (q & 3);
                    int rg = (rr >> 3) + 2*((q & 7) >> 2);
                    A2F[((t2*8 + (q >> 3))*32 + ln)*4 + rg] = __uint_as_float(f2tf32(d[nt][r]));
                }
        }
        __syncthreads();

        // ---- stage 2: ACC[(b,oo)][o23] += A2 @ W23_c ----
        const float* B2 = B2F + cb*4096;
        #pragma unroll
        for (int mt = 0; mt < 2; mt++) {
            const int tile = wid*2 + mt;
            #pragma unroll
            for (int kk = 0; kk < 8; kk++) {
                float4 af = *(const float4*)(A2F + ((tile*8 + kk)*32 + lane)*4);
                uint32_t a[4] = {__float_as_uint(af.x), __float_as_uint(af.y),
                                 __float_as_uint(af.z), __float_as_uint(af.w)};
                #pragma unroll
                for (int nt = 0; nt < 8; nt++) {
                    float2 bf = *(const float2*)(B2 + ((kk*8 + nt)*32 + lane)*2);
                    uint32_t b[2] = {__float_as_uint(bf.x), __float_as_uint(bf.y)};
                    mma1688(acc[mt][nt], a, b);
                }
            }
        }
        // no trailing sync: next-chunk top sync covers A2F WAR
    }

    // ---- epilogue: acc element (row'=(b,oo), col=o23) + bias -> out ----
    #pragma unroll
    for (int mt = 0; mt < 2; mt++) {
        const int tile = wid*2 + mt;
        #pragma unroll
        for (int nt = 0; nt < 8; nt++) {
            #pragma unroll
            for (int rp = 0; rp < 2; rp++) {
                int orow = tile*16 + g + 8*rp;
                int b  = orow >> 6, oo = orow & 63;
                int o23 = nt*8 + 2*tq;
                float2 bv = *(const float2*)(bias + oo*64 + o23);
                float2 w;
                w.x = acc[mt][nt][2*rp + 0] + bv.x;
                w.y = acc[mt][nt][2*rp + 1] + bv.y;
                *(float2*)(out + (b0 + b)*4096 + oo*64 + o23) = w;
            }
        }
    }
}

extern "C" void kernel_launch(void* const* d_in, const int* in_sizes, int n_in,
                              void* d_out, int out_size) {
    const float* x    = (const float*)d_in[0];
    const float* w0   = (const float*)d_in[1];
    const float* w1   = (const float*)d_in[2];
    const float* w2   = (const float*)d_in[3];
    const float* w3   = (const float*)d_in[4];
    const float* bias = (const float*)d_in[5];
    float* out = (float*)d_out;

    tt_pre<<<512, 256>>>(w0, w1, w2, w3);

    cudaFuncSetAttribute(tt_mma, cudaFuncAttributeMaxDynamicSharedMemorySize,
                         SMF_TOTAL * (int)sizeof(float));
    tt_mma<<<16384 / 4, THREADS, SMF_TOTAL * (int)sizeof(float)>>>(x, bias, out);
}

// round 6
// speedup vs baseline: 4.7796x; 1.2529x over previous
#include <cuda_runtime.h>
#include <cstdint>

#define THREADS 256

// ---------------- helpers ----------------
__device__ __forceinline__ uint32_t f2tf32(float f){
    uint32_t u; asm("cvt.rna.tf32.f32 %0, %1;" : "=r"(u) : "f"(f)); return u;
}
__device__ __forceinline__ uint32_t smem_u32(const void* p){
    uint32_t a;
    asm("{ .reg .u64 t; cvta.to.shared.u64 t, %1; cvt.u32.u64 %0, t; }" : "=r"(a) : "l"(p));
    return a;
}
__device__ __forceinline__ void mma1688(float d[4], const uint32_t a[4], const uint32_t b[2]){
    asm volatile("mma.sync.aligned.m16n8k8.row.col.f32.tf32.tf32.f32 "
        "{%0,%1,%2,%3}, {%4,%5,%6,%7}, {%8,%9}, {%0,%1,%2,%3};"
        : "+f"(d[0]), "+f"(d[1]), "+f"(d[2]), "+f"(d[3])
        : "r"(a[0]), "r"(a[1]), "r"(a[2]), "r"(a[3]), "r"(b[0]), "r"(b[1]));
}
#define CPA16(d, s)  asm volatile("cp.async.cg.shared.global [%0], [%1], 16;" :: "r"(d), "l"(s))
#define CPA_COMMIT() asm volatile("cp.async.commit_group;" ::: "memory")
#define CPA_WAIT0()  asm volatile("cp.async.wait_group 0;" ::: "memory")

// ---------------- merged weights, fragment-ordered, tf32-rounded ----------------
// 16 chunks (r2) x 4096 floats, mma.sync B-fragment order:
//   fi = ((kk*8 + nt)*32 + lane)*2 + reg ; k = kk*8 + (lane&3) + 4*reg, n = nt*8 + (lane>>2)
// gW01f: k = m (i0,i1), n = oo (o0,o1).   gW23f: k = q (i2,i3), n = o23 (o2,o3).
__device__ __align__(16) float gW01f[65536];
__device__ __align__(16) float gW23f[65536];

__global__ void tt_pre(const float* __restrict__ w0, const float* __restrict__ w1,
                       const float* __restrict__ w2, const float* __restrict__ w3) {
    int tid = blockIdx.x * blockDim.x + threadIdx.x;
    if (tid < 65536) {
        int c    = tid >> 12;
        int fi   = tid & 4095;
        int reg  = fi & 1;
        int lane = (fi >> 1) & 31;
        int nt   = (fi >> 6) & 7;
        int kk   = fi >> 9;
        int m  = kk*8 + (lane & 3) + 4*reg;
        int oo = nt*8 + (lane >> 2);
        int o0 = oo >> 3, o1 = oo & 7;
        int i0 = m >> 3,  i1 = m & 7;
        float s = 0.f;
        #pragma unroll
        for (int r1 = 0; r1 < 16; r1++)
            s += w0[(o0*16 + r1)*8 + i0] * w1[(o1*16 + c)*128 + r1*8 + i1];
        gW01f[c*4096 + fi] = __uint_as_float(f2tf32(s));
    } else if (tid < 131072) {
        int t    = tid - 65536;
        int c    = t >> 12;
        int fi   = t & 4095;
        int reg  = fi & 1;
        int lane = (fi >> 1) & 31;
        int nt   = (fi >> 6) & 7;
        int kk   = fi >> 9;
        int q   = kk*8 + (lane & 3) + 4*reg;
        int o23 = nt*8 + (lane >> 2);
        int o2 = o23 >> 3, o3 = o23 & 7;
        int i2 = q >> 3,   i3 = q & 7;
        float s = 0.f;
        #pragma unroll
        for (int r3 = 0; r3 < 16; r3++)
            s += w2[(o2*16 + r3)*128 + c*8 + i2] * w3[o3*128 + r3*8 + i3];
        gW23f[c*4096 + fi] = __uint_as_float(f2tf32(s));
    }
}

// ---------------- SMEM map (float indices) ----------------
// A1F [0, 16384)        : X fragments (rows (b,q), k=m), fragment layout
// A2F [16384, 33792)    : t1^T plain row-major, stride 68: A2F[row2*68 + q], row2=(b,oo)
// B1F [33792, +2*4096)  : W01 chunk double-buffer
// B2F [41984, +2*4096)  : W23 chunk double-buffer
#define A2_OFF 16384
#define A2_STRIDE 68
#define B1_OFF 33792
#define B2_OFF 41984
#define SMF_TOTAL 50176

__global__ __launch_bounds__(THREADS, 1)
void tt_mma(const float* __restrict__ x, const float* __restrict__ bias,
            float* __restrict__ out) {
    extern __shared__ float smf[];
    float* A1F = smf;
    float* A2F = smf + A2_OFF;
    float* B1F = smf + B1_OFF;
    float* B2F = smf + B2_OFF;

    const int tid  = threadIdx.x;
    const int wid  = tid >> 5;
    const int lane = tid & 31;
    const uint32_t sb  = smem_u32(smf);
    const uint32_t B1a = sb + B1_OFF*4u;
    const uint32_t B2a = sb + B2_OFF*4u;

    // prefetch weight chunk 0 (16KB each)
    {
        const float4* s01 = (const float4*)gW01f;
        const float4* s23 = (const float4*)gW23f;
        #pragma unroll
        for (int i = 0; i < 4; i++) CPA16(B1a + (tid + i*256)*16, s01 + tid + i*256);
        #pragma unroll
        for (int i = 0; i < 4; i++) CPA16(B2a + (tid + i*256)*16, s23 + tid + i*256);
        CPA_COMMIT();
    }

    // ---- stage X (4 batch rows) into A1 fragment layout (tf32-rounded) ----
    const long long b0 = (long long)blockIdx.x * 4;
    {
        const float4* xp = (const float4*)(x + b0 * 4096);
        #pragma unroll 4
        for (int e = tid; e < 4096; e += THREADS) {
            float4 v = xp[e];
            int idx = e * 4;
            int b = idx >> 12, m = (idx >> 6) & 63, q = idx & 63;  // q % 4 == 0
            int kk = m >> 3;
            int rhi = ((m & 7) >> 2);
            int ld  = (m & 3);
            float vv[4] = {v.x, v.y, v.z, v.w};
            #pragma unroll
            for (int j = 0; j < 4; j++) {
                int row = b*64 + q + j;
                int tile = row >> 4, r = row & 15;
                int ln = (r & 7)*4 + ld;
                int rg = (r >> 3) + 2*rhi;
                A1F[((tile*8 + kk)*32 + ln)*4 + rg] = __uint_as_float(f2tf32(vv[j]));
            }
        }
    }

    float acc[2][8][4];
    #pragma unroll
    for (int mt = 0; mt < 2; mt++)
        #pragma unroll
        for (int nt = 0; nt < 8; nt++)
            #pragma unroll
            for (int r = 0; r < 4; r++) acc[mt][nt][r] = 0.f;

    const int g = lane >> 2, tq = lane & 3;

    for (int c = 0; c < 16; c++) {
        const int cb = c & 1;
        CPA_WAIT0();
        __syncthreads();   // weights visible; A2F WAR vs prev stage-2 reads cleared

        if (c < 15) {
            const int nb = cb ^ 1;
            const float4* s01 = (const float4*)(gW01f + (c + 1)*4096);
            const float4* s23 = (const float4*)(gW23f + (c + 1)*4096);
            #pragma unroll
            for (int i = 0; i < 4; i++) CPA16(B1a + nb*16384 + (tid + i*256)*16, s01 + tid + i*256);
            #pragma unroll
            for (int i = 0; i < 4; i++) CPA16(B2a + nb*16384 + (tid + i*256)*16, s23 + tid + i*256);
            CPA_COMMIT();
        }

        // ---- stage 1: D1[(b,q)][oo] = A1 @ W01_c (kk-outer, B hoisted across mt) ----
        const float* B1 = B1F + cb*4096;
        float d[2][8][4];
        #pragma unroll
        for (int mt = 0; mt < 2; mt++)
            #pragma unroll
            for (int nt = 0; nt < 8; nt++)
                #pragma unroll
                for (int r = 0; r < 4; r++) d[mt][nt][r] = 0.f;

        #pragma unroll
        for (int kk = 0; kk < 8; kk++) {
            uint32_t bfr[8][2];
            #pragma unroll
            for (int nt = 0; nt < 8; nt++) {
                float2 bf = *(const float2*)(B1 + ((kk*8 + nt)*32 + lane)*2);
                bfr[nt][0] = __float_as_uint(bf.x);
                bfr[nt][1] = __float_as_uint(bf.y);
            }
            #pragma unroll
            for (int mt = 0; mt < 2; mt++) {
                const int tile = wid*2 + mt;
                float4 af = *(const float4*)(A1F + ((tile*8 + kk)*32 + lane)*4);
                uint32_t a[4] = {__float_as_uint(af.x), __float_as_uint(af.y),
                                 __float_as_uint(af.z), __float_as_uint(af.w)};
                #pragma unroll
                for (int nt = 0; nt < 8; nt++)
                    mma1688(d[mt][nt], a, bfr[nt]);
            }
        }

        // ---- scatter-transpose into A2 row-major (stride 68): conflict-free ----
        // element (row=(b,q), col=oo) -> A2F[(b*64+oo)*68 + q], b = tile>>2
        #pragma unroll
        for (int mt = 0; mt < 2; mt++) {
            const int tile = wid*2 + mt;
            const int bt   = tile >> 2;          // batch index of this tile (FIX)
            #pragma unroll
            for (int nt = 0; nt < 8; nt++)
                #pragma unroll
                for (int r = 0; r < 4; r++) {
                    int orow = tile*16 + g + 8*(r >> 1);
                    int q    = orow & 63;
                    int oo   = nt*8 + 2*tq + (r & 1);
                    A2F[(bt*64 + oo)*A2_STRIDE + q] =
                        __uint_as_float(f2tf32(d[mt][nt][r]));
                }
        }
        __syncthreads();

        // ---- stage 2: ACC[(b,oo)][o23] += A2 @ W23_c (kk-outer, B hoisted) ----
        const float* B2 = B2F + cb*4096;
        #pragma unroll
        for (int kk = 0; kk < 8; kk++) {
            uint32_t bfr[8][2];
            #pragma unroll
            for (int nt = 0; nt < 8; nt++) {
                float2 bf = *(const float2*)(B2 + ((kk*8 + nt)*32 + lane)*2);
                bfr[nt][0] = __float_as_uint(bf.x);
                bfr[nt][1] = __float_as_uint(bf.y);
            }
            #pragma unroll
            for (int mt = 0; mt < 2; mt++) {
                const int tile = wid*2 + mt;
                const float* base = A2F + (tile*16 + g)*A2_STRIDE + kk*8 + tq;
                uint32_t a[4];
                a[0] = __float_as_uint(base[0]);
                a[1] = __float_as_uint(base[8*A2_STRIDE]);
                a[2] = __float_as_uint(base[4]);
                a[3] = __float_as_uint(base[8*A2_STRIDE + 4]);
                #pragma unroll
                for (int nt = 0; nt < 8; nt++)
                    mma1688(acc[mt][nt], a, bfr[nt]);
            }
        }
        // no trailing sync: next-chunk top sync covers A2F WAR
    }

    // ---- epilogue: acc element (row'=(b,oo), col=o23) + bias -> out ----
    #pragma unroll
    for (int mt = 0; mt < 2; mt++) {
        const int tile = wid*2 + mt;
        #pragma unroll
        for (int nt = 0; nt < 8; nt++) {
            #pragma unroll
            for (int rp = 0; rp < 2; rp++) {
                int orow = tile*16 + g + 8*rp;
                int b  = orow >> 6, oo = orow & 63;
                int o23 = nt*8 + 2*tq;
                float2 bv = *(const float2*)(bias + oo*64 + o23);
                float2 w;
                w.x = acc[mt][nt][2*rp + 0] + bv.x;
                w.y = acc[mt][nt][2*rp + 1] + bv.y;
                *(float2*)(out + (b0 + b)*4096 + oo*64 + o23) = w;
            }
        }
    }
}

extern "C" void kernel_launch(void* const* d_in, const int* in_sizes, int n_in,
                              void* d_out, int out_size) {
    const float* x    = (const float*)d_in[0];
    const float* w0   = (const float*)d_in[1];
    const float* w1   = (const float*)d_in[2];
    const float* w2   = (const float*)d_in[3];
    const float* w3   = (const float*)d_in[4];
    const float* bias = (const float*)d_in[5];
    float* out = (float*)d_out;

    tt_pre<<<512, 256>>>(w0, w1, w2, w3);

    cudaFuncSetAttribute(tt_mma, cudaFuncAttributeMaxDynamicSharedMemorySize,
                         SMF_TOTAL * (int)sizeof(float));
    tt_mma<<<16384 / 4, THREADS, SMF_TOTAL * (int)sizeof(float)>>>(x, bias, out);
}

// round 7
// speedup vs baseline: 5.0115x; 1.0485x over previous
#include <cuda_runtime.h>
#include <cstdint>

#define THREADS 256

// ---------------- helpers ----------------
__device__ __forceinline__ uint32_t f2tf32(float f){
    uint32_t u; asm("cvt.rna.tf32.f32 %0, %1;" : "=r"(u) : "f"(f)); return u;
}
__device__ __forceinline__ uint32_t smem_u32(const void* p){
    uint32_t a;
    asm("{ .reg .u64 t; cvta.to.shared.u64 t, %1; cvt.u32.u64 %0, t; }" : "=r"(a) : "l"(p));
    return a;
}
__device__ __forceinline__ void mma1688(float d[4], const uint32_t a[4], const uint32_t b0, const uint32_t b1){
    asm volatile("mma.sync.aligned.m16n8k8.row.col.f32.tf32.tf32.f32 "
        "{%0,%1,%2,%3}, {%4,%5,%6,%7}, {%8,%9}, {%0,%1,%2,%3};"
        : "+f"(d[0]), "+f"(d[1]), "+f"(d[2]), "+f"(d[3])
        : "r"(a[0]), "r"(a[1]), "r"(a[2]), "r"(a[3]), "r"(b0), "r"(b1));
}
#define CPA16(d, s)  asm volatile("cp.async.cg.shared.global [%0], [%1], 16;" :: "r"(d), "l"(s))
#define CPA_COMMIT() asm volatile("cp.async.commit_group;" ::: "memory")
#define CPA_WAIT0()  asm volatile("cp.async.wait_group 0;" ::: "memory")

// ---------------- merged weights, fragment-ordered, tf32-rounded ----------------
// gW01f (stage-1 B operand), 16 chunks x 4096, B-fragment order:
//   fi = ((kk*8 + nt)*32 + lane)*2 + reg ; k=m = kk*8+(lane&3)+4*reg, n=oo = nt*8+(lane>>2)
// gW23f (stage-2 A operand), 16 chunks x 4096, A-fragment order:
//   fi = ((mt*8 + kk)*32 + lane)*4 + r ; o23 = mt*16+(lane>>2)+8*(r&1), k=q = kk*8+(lane&3)+4*(r>>1)
__device__ __align__(16) float gW01f[65536];
__device__ __align__(16) float gW23f[65536];

__global__ void tt_pre(const float* __restrict__ w0, const float* __restrict__ w1,
                       const float* __restrict__ w2, const float* __restrict__ w3) {
    int tid = blockIdx.x * blockDim.x + threadIdx.x;
    if (tid < 65536) {
        int c    = tid >> 12;
        int fi   = tid & 4095;
        int reg  = fi & 1;
        int lane = (fi >> 1) & 31;
        int nt   = (fi >> 6) & 7;
        int kk   = fi >> 9;
        int m  = kk*8 + (lane & 3) + 4*reg;
        int oo = nt*8 + (lane >> 2);
        int o0 = oo >> 3, o1 = oo & 7;
        int i0 = m >> 3,  i1 = m & 7;
        float s = 0.f;
        #pragma unroll
        for (int r1 = 0; r1 < 16; r1++)
            s += w0[(o0*16 + r1)*8 + i0] * w1[(o1*16 + c)*128 + r1*8 + i1];
        gW01f[c*4096 + fi] = __uint_as_float(f2tf32(s));
    } else if (tid < 131072) {
        int t    = tid - 65536;
        int c    = t >> 12;
        int fi   = t & 4095;
        int r    = fi & 3;
        int lane = (fi >> 2) & 31;
        int kk   = (fi >> 7) & 7;
        int mt   = fi >> 10;
        int o23 = mt*16 + (lane >> 2) + 8*(r & 1);
        int q   = kk*8 + (lane & 3) + 4*(r >> 1);
        int o2 = o23 >> 3, o3 = o23 & 7;
        int i2 = q >> 3,   i3 = q & 7;
        float s = 0.f;
        #pragma unroll
        for (int r3 = 0; r3 < 16; r3++)
            s += w2[(o2*16 + r3)*128 + c*8 + i2] * w3[o3*128 + r3*8 + i3];
        gW23f[c*4096 + fi] = __uint_as_float(f2tf32(s));
    }
}

// ---------------- SMEM map (float indices) ----------------
// A1F [0, 16384)      : X fragments (rows (b,q), k=m); reused as reduction buffer at the end
// B1F [16384, +8192)  : W01 chunk double-buffer
// B2F [24576, +8192)  : W23 chunk double-buffer
#define B1_OFF 16384
#define B2_OFF 24576
#define SMF_TOTAL 32768

__global__ __launch_bounds__(THREADS, 1)
void tt_mma(const float* __restrict__ x, const float* __restrict__ bias,
            float* __restrict__ out) {
    extern __shared__ float smf[];
    float* A1F = smf;
    float* B1F = smf + B1_OFF;
    float* B2F = smf + B2_OFF;

    const int tid  = threadIdx.x;
    const int wid  = tid >> 5;
    const int lane = tid & 31;
    const uint32_t sb  = smem_u32(smf);
    const uint32_t B1a = sb + B1_OFF*4u;
    const uint32_t B2a = sb + B2_OFF*4u;

    // prefetch weight chunk 0 (16KB each = 1024 float4)
    {
        const float4* s01 = (const float4*)gW01f;
        const float4* s23 = (const float4*)gW23f;
        #pragma unroll
        for (int i = 0; i < 4; i++) CPA16(B1a + (tid + i*256)*16, s01 + tid + i*256);
        #pragma unroll
        for (int i = 0; i < 4; i++) CPA16(B2a + (tid + i*256)*16, s23 + tid + i*256);
        CPA_COMMIT();
    }

    // ---- stage X (4 batch rows) into A1 fragment layout (tf32-rounded) ----
    const long long b0 = (long long)blockIdx.x * 4;
    {
        const float4* xp = (const float4*)(x + b0 * 4096);
        #pragma unroll 4
        for (int e = tid; e < 4096; e += THREADS) {
            float4 v = xp[e];
            int idx = e * 4;
            int b = idx >> 12, m = (idx >> 6) & 63, q = idx & 63;  // q % 4 == 0
            int kk = m >> 3;
            int rhi = ((m & 7) >> 2);
            int ld  = (m & 3);
            float vv[4] = {v.x, v.y, v.z, v.w};
            #pragma unroll
            for (int j = 0; j < 4; j++) {
                int row = b*64 + q + j;
                int tile = row >> 4, r = row & 15;
                int ln = (r & 7)*4 + ld;
                int rg = (r >> 3) + 2*rhi;
                A1F[((tile*8 + kk)*32 + ln)*4 + rg] = __uint_as_float(f2tf32(vv[j]));
            }
        }
    }

    // Stage-2 accumulators: full [o23(4 tiles) x oo(8 tiles)] partial (this warp's q-slice)
    float acc[4][8][4];
    #pragma unroll
    for (int mt = 0; mt < 4; mt++)
        #pragma unroll
        for (int nt = 0; nt < 8; nt++)
            #pragma unroll
            for (int r = 0; r < 4; r++) acc[mt][nt][r] = 0.f;

    // shuffle source lanes for d -> B-fragment conversion
    const int src0 = 4*(lane & 3) + ((lane >> 2) >> 1);
    const int src1 = src0 + 16;
    const int colpar = (lane >> 2) & 1;

    for (int c = 0; c < 16; c++) {
        const int cb = c & 1;
        CPA_WAIT0();
        __syncthreads();   // weights visible; WAR on weight buffers cleared

        if (c < 15) {
            const int nb = cb ^ 1;
            const float4* s01 = (const float4*)(gW01f + (c + 1)*4096);
            const float4* s23 = (const float4*)(gW23f + (c + 1)*4096);
            #pragma unroll
            for (int i = 0; i < 4; i++) CPA16(B1a + nb*16384 + (tid + i*256)*16, s01 + tid + i*256);
            #pragma unroll
            for (int i = 0; i < 4; i++) CPA16(B2a + nb*16384 + (tid + i*256)*16, s23 + tid + i*256);
            CPA_COMMIT();
        }

        const float* B1 = B1F + cb*4096;
        const float* B2 = B2F + cb*4096;

        #pragma unroll
        for (int mt2 = 0; mt2 < 2; mt2++) {
            const int tile = wid*2 + mt2;          // rows (b = tile>>2, q-slice (tile&3)*16)

            // ---- stage 1: d[16 x 64] = X_tile @ W01_c ----
            float d[8][4];
            #pragma unroll
            for (int nt = 0; nt < 8; nt++)
                #pragma unroll
                for (int r = 0; r < 4; r++) d[nt][r] = 0.f;

            #pragma unroll
            for (int kk = 0; kk < 8; kk++) {
                float4 af = *(const float4*)(A1F + ((tile*8 + kk)*32 + lane)*4);
                uint32_t a[4] = {__float_as_uint(af.x), __float_as_uint(af.y),
                                 __float_as_uint(af.z), __float_as_uint(af.w)};
                #pragma unroll
                for (int nt = 0; nt < 8; nt++) {
                    float2 bf = *(const float2*)(B1 + ((kk*8 + nt)*32 + lane)*2);
                    mma1688(d[nt], a, __float_as_uint(bf.x), __float_as_uint(bf.y));
                }
            }

            // round t1 to tf32 in registers
            #pragma unroll
            for (int nt = 0; nt < 8; nt++)
                #pragma unroll
                for (int r = 0; r < 4; r++)
                    d[nt][r] = __uint_as_float(f2tf32(d[nt][r]));

            // ---- stage 2: ACC[o23 x oo] += W23_c(A-frag) @ d(B-frag via shuffles) ----
            #pragma unroll
            for (int kkp = 0; kkp < 2; kkp++) {
                const int kkg = (tile & 3)*2 + kkp;   // global q k-step of this 8-row slice
                // build B-fragments from d: element (k=q_local, n=oo)
                uint32_t bs[8][2];
                #pragma unroll
                for (int nt = 0; nt < 8; nt++) {
                    float v00 = __shfl_sync(0xffffffffu, d[nt][2*kkp + 0], src0);
                    float v01 = __shfl_sync(0xffffffffu, d[nt][2*kkp + 1], src0);
                    float v10 = __shfl_sync(0xffffffffu, d[nt][2*kkp + 0], src1);
                    float v11 = __shfl_sync(0xffffffffu, d[nt][2*kkp + 1], src1);
                    bs[nt][0] = __float_as_uint(colpar ? v01 : v00);
                    bs[nt][1] = __float_as_uint(colpar ? v11 : v10);
                }
                #pragma unroll
                for (int mt = 0; mt < 4; mt++) {
                    float4 af = *(const float4*)(B2 + ((mt*8 + kkg)*32 + lane)*4);
                    uint32_t a[4] = {__float_as_uint(af.x), __float_as_uint(af.y),
                                     __float_as_uint(af.z), __float_as_uint(af.w)};
                    #pragma unroll
                    for (int nt = 0; nt < 8; nt++)
                        mma1688(acc[mt][nt], a, bs[nt][0], bs[nt][1]);
                }
            }
        }
    }

    // ---- cross-warp reduction (warp pair per batch) + epilogue ----
    __syncthreads();        // all warps done reading A1F; reuse it as reduction buffer
    if (wid & 1) {
        float* red = smf + (wid >> 1) * 4096;
        #pragma unroll
        for (int mt = 0; mt < 4; mt++)
            #pragma unroll
            for (int nt = 0; nt < 8; nt++)
                *(float4*)(red + ((mt*8 + nt)*32 + lane)*4) =
                    make_float4(acc[mt][nt][0], acc[mt][nt][1], acc[mt][nt][2], acc[mt][nt][3]);
    }
    __syncthreads();
    if (!(wid & 1)) {
        const int b = wid >> 1;
        const float* red = smf + b * 4096;
        const int g = lane >> 2, tq = lane & 3;
        float* ob = out + (b0 + b) * 4096;
        #pragma unroll
        for (int mt = 0; mt < 4; mt++)
            #pragma unroll
            for (int nt = 0; nt < 8; nt++) {
                float4 pv = *(const float4*)(red + ((mt*8 + nt)*32 + lane)*4);
                float s[4] = {acc[mt][nt][0] + pv.x, acc[mt][nt][1] + pv.y,
                              acc[mt][nt][2] + pv.z, acc[mt][nt][3] + pv.w};
                #pragma unroll
                for (int r = 0; r < 4; r++) {
                    int o23 = mt*16 + g + 8*(r >> 1);
                    int oo  = nt*8 + 2*tq + (r & 1);
                    int col = oo*64 + o23;
                    ob[col] = s[r] + __ldg(bias + col);
                }
            }
    }
}

extern "C" void kernel_launch(void* const* d_in, const int* in_sizes, int n_in,
                              void* d_out, int out_size) {
    const float* x    = (const float*)d_in[0];
    const float* w0   = (const float*)d_in[1];
    const float* w1   = (const float*)d_in[2];
    const float* w2   = (const float*)d_in[3];
    const float* w3   = (const float*)d_in[4];
    const float* bias = (const float*)d_in[5];
    float* out = (float*)d_out;

    tt_pre<<<512, 256>>>(w0, w1, w2, w3);

    cudaFuncSetAttribute(tt_mma, cudaFuncAttributeMaxDynamicSharedMemorySize,
                         SMF_TOTAL * (int)sizeof(float));
    tt_mma<<<16384 / 4, THREADS, SMF_TOTAL * (int)sizeof(float)>>>(x, bias, out);
}